// round 14
// baseline (speedup 1.0000x reference)
#include <cuda_runtime.h>
#include <cuda_bf16.h>
#include <math.h>

#define BATCH   256
#define NPTS    8192
#define THREADS 512
#define NCH     ((NPTS * 3) / 12)        // 2048 chunks of 4 points
#define ITERS   (NCH / THREADS)          // 4
#define CLAMP_V 10.0f

// Scratch (no allocations allowed -> __device__ globals)
__device__ float d_partial[BATCH];       // per-batch clamped-distance sums
__device__ int   d_count;                // last-block counter (reset each replay)

__device__ __forceinline__ float warpSum(float v) {
#pragma unroll
    for (int o = 16; o; o >>= 1) v += __shfl_down_sync(0xffffffffu, v, o);
    return v;
}

// ---------------------------------------------------------------------------
// fp32 Kabsch solve from the 15 reduced sums (single thread).
// H = M - sumA sumB^T / N ; Jacobi eig of K = H^T H -> V, lam ; u_k = H v_k/sig
// R = sum_k s_k v_k u_k^T (sign flip on SMALLEST sigma iff det(H) < 0)
// == V diag(1,1,s) U^T as in the reference. t = cB - R cA. 5 sweeps suffice
// (validated: rel_err ~5e-5 vs 1e-3 tolerance).
// ---------------------------------------------------------------------------
__device__ void kabsch_solve(const float* __restrict__ s, float* __restrict__ rt) {
    const float invN = 1.0f / (float)NPTS;
    float sA[3] = {s[0], s[1], s[2]};
    float sB[3] = {s[3], s[4], s[5]};
    float H[3][3];
#pragma unroll
    for (int i = 0; i < 3; i++)
#pragma unroll
        for (int j = 0; j < 3; j++)
            H[i][j] = s[6 + i * 3 + j] - sA[i] * sB[j] * invN;

    float K[3][3];
#pragma unroll
    for (int i = 0; i < 3; i++)
#pragma unroll
        for (int j = 0; j < 3; j++)
            K[i][j] = H[0][i]*H[0][j] + H[1][i]*H[1][j] + H[2][i]*H[2][j];

    float V[3][3] = {{1,0,0},{0,1,0},{0,0,1}};
    const int PP[3] = {0, 0, 1};
    const int QQ[3] = {1, 2, 2};
    for (int sweep = 0; sweep < 5; sweep++) {
#pragma unroll
        for (int pair = 0; pair < 3; pair++) {
            const int p = PP[pair], q = QQ[pair];
            float apq = K[p][q];
            if (fabsf(apq) <= 1e-10f * (fabsf(K[p][p]) + fabsf(K[q][q]))) continue;
            float theta = (K[q][q] - K[p][p]) / (2.0f * apq);
            float t = (theta >= 0.0f) ? 1.0f / (theta + sqrtf(1.0f + theta * theta))
                                      : 1.0f / (theta - sqrtf(1.0f + theta * theta));
            float c = rsqrtf(1.0f + t * t);
            float sn = t * c;
#pragma unroll
            for (int k = 0; k < 3; k++) {
                float kp = K[k][p], kq = K[k][q];
                K[k][p] = c * kp - sn * kq;
                K[k][q] = sn * kp + c * kq;
            }
#pragma unroll
            for (int k = 0; k < 3; k++) {
                float pk = K[p][k], qk = K[q][k];
                K[p][k] = c * pk - sn * qk;
                K[q][k] = sn * pk + c * qk;
            }
#pragma unroll
            for (int k = 0; k < 3; k++) {
                float vp_ = V[k][p], vq_ = V[k][q];
                V[k][p] = c * vp_ - sn * vq_;
                V[k][q] = sn * vp_ + c * vq_;
            }
        }
    }

    float lam[3] = {K[0][0], K[1][1], K[2][2]};
    int imin = 0;
    if (lam[1] < lam[imin]) imin = 1;
    if (lam[2] < lam[imin]) imin = 2;

    float detH = H[0][0]*(H[1][1]*H[2][2] - H[1][2]*H[2][1])
               - H[0][1]*(H[1][0]*H[2][2] - H[1][2]*H[2][0])
               + H[0][2]*(H[1][0]*H[2][1] - H[1][1]*H[2][0]);

    float R[3][3] = {{0,0,0},{0,0,0},{0,0,0}};
#pragma unroll
    for (int k = 0; k < 3; k++) {
        float v0 = V[0][k], v1 = V[1][k], v2 = V[2][k];
        float hv0 = H[0][0]*v0 + H[0][1]*v1 + H[0][2]*v2;
        float hv1 = H[1][0]*v0 + H[1][1]*v1 + H[1][2]*v2;
        float hv2 = H[2][0]*v0 + H[2][1]*v1 + H[2][2]*v2;
        float coef = rsqrtf(fmaxf(lam[k], 1e-30f));
        if (k == imin && detH < 0.0f) coef = -coef;
        R[0][0] += coef * v0 * hv0; R[0][1] += coef * v0 * hv1; R[0][2] += coef * v0 * hv2;
        R[1][0] += coef * v1 * hv0; R[1][1] += coef * v1 * hv1; R[1][2] += coef * v1 * hv2;
        R[2][0] += coef * v2 * hv0; R[2][1] += coef * v2 * hv1; R[2][2] += coef * v2 * hv2;
    }

    float cA0 = sA[0]*invN, cA1 = sA[1]*invN, cA2 = sA[2]*invN;
    float cB0 = sB[0]*invN, cB1 = sB[1]*invN, cB2 = sB[2]*invN;

#pragma unroll
    for (int i = 0; i < 3; i++)
#pragma unroll
        for (int j = 0; j < 3; j++)
            rt[i * 3 + j] = R[i][j];
    rt[9]  = cB0 - (R[0][0]*cA0 + R[0][1]*cA1 + R[0][2]*cA2);
    rt[10] = cB1 - (R[1][0]*cA0 + R[1][1]*cA1 + R[1][2]*cA2);
    rt[11] = cB2 - (R[2][0]*cA0 + R[2][1]*cA1 + R[2][2]*cA2);
}

// ---------------------------------------------------------------------------
// Fused kernel: one block per batch, 512 threads, NO smem data cache.
// Phase A: stream pred/true (float4 loop), 15-term covariance reduction.
// Solve:   thread 0 fp32 Kabsch -> R,t in shared (co-resident block streams
//          meanwhile; 2 CTAs/SM via launch_bounds(512,2)).
// Phase B: re-read both arrays (this block's 192 KB is L2-hot -- it just
//          streamed it), clamped distances, per-batch sum, global last-block
//          fixed-order mean.
// aligned_j = sum_i p_i * R[i][j] + t[j]   (pred @ R, as in reference)
// ---------------------------------------------------------------------------
__global__ __launch_bounds__(THREADS, 2)
void fused_fape(const float* __restrict__ pred, const float* __restrict__ truep,
                float* __restrict__ out) {
    const int b = blockIdx.x;
    const float* pp = pred  + (size_t)b * NPTS * 3;
    const float* qq = truep + (size_t)b * NPTS * 3;
    const int lane = threadIdx.x & 31, w = threadIdx.x >> 5;

    __shared__ float ws[16][15];
    __shared__ float sh15[15];
    __shared__ float sRT[12];
    __shared__ float ws2[16];
    __shared__ bool  amLast;

    // ---------------- Phase A: covariance accumulation ----------------
    float v15[15];
#pragma unroll
    for (int i = 0; i < 15; i++) v15[i] = 0.f;

#pragma unroll
    for (int it = 0; it < ITERS; it++) {
        const int c = threadIdx.x + it * THREADS;          // chunk of 4 points
        const float4* vp = reinterpret_cast<const float4*>(pp + c * 12);
        const float4* vq = reinterpret_cast<const float4*>(qq + c * 12);
        float4 a0 = vp[0], a1 = vp[1], a2 = vp[2];
        float4 b0 = vq[0], b1 = vq[1], b2 = vq[2];
        float px[4] = {a0.x, a0.w, a1.z, a2.y};
        float py[4] = {a0.y, a1.x, a1.w, a2.z};
        float pz[4] = {a0.z, a1.y, a2.x, a2.w};
        float qx[4] = {b0.x, b0.w, b1.z, b2.y};
        float qy[4] = {b0.y, b1.x, b1.w, b2.z};
        float qz[4] = {b0.z, b1.y, b2.x, b2.w};
#pragma unroll
        for (int i = 0; i < 4; i++) {
            v15[0] += px[i]; v15[1] += py[i]; v15[2] += pz[i];
            v15[3] += qx[i]; v15[4] += qy[i]; v15[5] += qz[i];
            v15[6]  += px[i]*qx[i]; v15[7]  += px[i]*qy[i]; v15[8]  += px[i]*qz[i];
            v15[9]  += py[i]*qx[i]; v15[10] += py[i]*qy[i]; v15[11] += py[i]*qz[i];
            v15[12] += pz[i]*qx[i]; v15[13] += pz[i]*qy[i]; v15[14] += pz[i]*qz[i];
        }
    }

#pragma unroll
    for (int q = 0; q < 15; q++) {
        float r = warpSum(v15[q]);
        if (lane == 0) ws[w][q] = r;
    }
    __syncthreads();
    if (threadIdx.x < 15) {
        float tot = 0.f;
#pragma unroll
        for (int i = 0; i < 16; i++) tot += ws[i][threadIdx.x];
        sh15[threadIdx.x] = tot;
    }
    __syncthreads();

    // ---------------- Kabsch solve -> shared R,t ----------------
    if (threadIdx.x == 0) kabsch_solve(sh15, sRT);
    __syncthreads();

    const float R00=sRT[0], R01=sRT[1], R02=sRT[2],
                R10=sRT[3], R11=sRT[4], R12=sRT[5],
                R20=sRT[6], R21=sRT[7], R22=sRT[8],
                t0 =sRT[9], t1 =sRT[10], t2 =sRT[11];

    // ---------------- Phase B: distances (L2-hot re-read) ----------------
    float acc = 0.f;
#pragma unroll
    for (int it = 0; it < ITERS; it++) {
        const int c = threadIdx.x + it * THREADS;
        const float4* vp = reinterpret_cast<const float4*>(pp + c * 12);
        const float4* vq = reinterpret_cast<const float4*>(qq + c * 12);
        float4 a0 = vp[0], a1 = vp[1], a2 = vp[2];
        float4 b0 = vq[0], b1 = vq[1], b2 = vq[2];
        float px[4] = {a0.x, a0.w, a1.z, a2.y};
        float py[4] = {a0.y, a1.x, a1.w, a2.z};
        float pz[4] = {a0.z, a1.y, a2.x, a2.w};
        float qx[4] = {b0.x, b0.w, b1.z, b2.y};
        float qy[4] = {b0.y, b1.x, b1.w, b2.z};
        float qz[4] = {b0.z, b1.y, b2.x, b2.w};
#pragma unroll
        for (int i = 0; i < 4; i++) {
            float dx = px[i]*R00 + py[i]*R10 + pz[i]*R20 + t0 - qx[i];
            float dy = px[i]*R01 + py[i]*R11 + pz[i]*R21 + t1 - qy[i];
            float dz = px[i]*R02 + py[i]*R12 + pz[i]*R22 + t2 - qz[i];
            float d = sqrtf(dx*dx + dy*dy + dz*dz);
            acc += fminf(d, CLAMP_V);
        }
    }

    float r = warpSum(acc);
    if (lane == 0) ws2[w] = r;
    __syncthreads();
    if (threadIdx.x == 0) {
        float t = 0.f;
#pragma unroll
        for (int i = 0; i < 16; i++) t += ws2[i];
        d_partial[b] = t;
        __threadfence();
        int prev = atomicAdd(&d_count, 1);
        amLast = (prev == BATCH - 1);
    }
    __syncthreads();

    // Deterministic final reduce by the last-arriving block (fixed order).
    if (amLast) {
        __threadfence();
        float v = (threadIdx.x < BATCH) ? d_partial[threadIdx.x] : 0.f;
        __shared__ float fs[16];
        float rr = warpSum(v);
        if (lane == 0) fs[w] = rr;
        __syncthreads();
        if (threadIdx.x == 0) {
            float tot = 0.f;
#pragma unroll
            for (int i = 0; i < 8; i++) tot += fs[i];   // first 8 warps hold 256 values
            out[0] = tot / ((float)BATCH * (float)NPTS);
            d_count = 0;                                // reset for next replay
        }
    }
}

extern "C" void kernel_launch(void* const* d_in, const int* in_sizes, int n_in,
                              void* d_out, int out_size) {
    // Inputs in metadata order: pred_frames, true_frames, pred_pos, true_pos.
    // Select the two [B,N,3] arrays (size B*N*3) in order; frames stay untouched.
    const int POS_ELEMS = BATCH * NPTS * 3;
    const float* pred_pos = nullptr;
    const float* true_pos = nullptr;
    for (int i = 0; i < n_in; i++) {
        if (in_sizes[i] == POS_ELEMS) {
            if (!pred_pos)      pred_pos = (const float*)d_in[i];
            else if (!true_pos) true_pos = (const float*)d_in[i];
        }
    }
    if (!pred_pos || !true_pos) {
        pred_pos = (const float*)d_in[2];
        true_pos = (const float*)d_in[3];
    }

    fused_fape<<<BATCH, THREADS>>>(pred_pos, true_pos, (float*)d_out);
}

// round 15
// speedup vs baseline: 1.2035x; 1.2035x over previous
#include <cuda_runtime.h>
#include <cuda_bf16.h>
#include <math.h>

#define BATCH   256
#define NPTS    8192
#define THREADS 512
#define NCH     ((NPTS * 3) / 12)        // 2048 chunks of 4 points
#define ITERS   (NCH / THREADS)          // 4
#define CLAMP_V 10.0f

// Scratch (no allocations allowed -> __device__ globals)
__device__ float d_RT[BATCH * 12];       // per batch: R row-major [9], t [3]
__device__ float d_partial[BATCH];       // per-batch clamped-distance sums
__device__ int   d_count;                // last-block counter (reset each replay)

__device__ __forceinline__ float warpSum(float v) {
#pragma unroll
    for (int o = 16; o; o >>= 1) v += __shfl_down_sync(0xffffffffu, v, o);
    return v;
}

// ---------------------------------------------------------------------------
// fp32 Kabsch solve from the 15 reduced sums (single thread).
// H = M - sumA sumB^T / N ; Jacobi eig of K = H^T H -> V, lam ; u_k = H v_k/sig
// R = sum_k s_k v_k u_k^T (sign flip on SMALLEST sigma iff det(H) < 0)
// == V diag(1,1,s) U^T as in the reference. t = cB - R cA.
// 5 sweeps (validated rel_err ~5e-5); __fdividef replaces the two IEEE divides
// per rotation (~130cyc -> ~20cyc each) to shorten the serial dependence chain.
// ---------------------------------------------------------------------------
__device__ void kabsch_solve(const float* __restrict__ s, float* __restrict__ rt) {
    const float invN = 1.0f / (float)NPTS;
    float sA[3] = {s[0], s[1], s[2]};
    float sB[3] = {s[3], s[4], s[5]};
    float H[3][3];
#pragma unroll
    for (int i = 0; i < 3; i++)
#pragma unroll
        for (int j = 0; j < 3; j++)
            H[i][j] = s[6 + i * 3 + j] - sA[i] * sB[j] * invN;

    float K[3][3];
#pragma unroll
    for (int i = 0; i < 3; i++)
#pragma unroll
        for (int j = 0; j < 3; j++)
            K[i][j] = H[0][i]*H[0][j] + H[1][i]*H[1][j] + H[2][i]*H[2][j];

    float V[3][3] = {{1,0,0},{0,1,0},{0,0,1}};
    const int PP[3] = {0, 0, 1};
    const int QQ[3] = {1, 2, 2};
    for (int sweep = 0; sweep < 5; sweep++) {
#pragma unroll
        for (int pair = 0; pair < 3; pair++) {
            const int p = PP[pair], q = QQ[pair];
            float apq = K[p][q];
            if (fabsf(apq) <= 1e-10f * (fabsf(K[p][p]) + fabsf(K[q][q]))) continue;
            float theta = __fdividef(K[q][q] - K[p][p], 2.0f * apq);
            float den = (theta >= 0.0f) ? (theta + sqrtf(1.0f + theta * theta))
                                        : (theta - sqrtf(1.0f + theta * theta));
            float t = __fdividef(1.0f, den);
            float c = rsqrtf(1.0f + t * t);
            float sn = t * c;
#pragma unroll
            for (int k = 0; k < 3; k++) {
                float kp = K[k][p], kq = K[k][q];
                K[k][p] = c * kp - sn * kq;
                K[k][q] = sn * kp + c * kq;
            }
#pragma unroll
            for (int k = 0; k < 3; k++) {
                float pk = K[p][k], qk = K[q][k];
                K[p][k] = c * pk - sn * qk;
                K[q][k] = sn * pk + c * qk;
            }
#pragma unroll
            for (int k = 0; k < 3; k++) {
                float vp_ = V[k][p], vq_ = V[k][q];
                V[k][p] = c * vp_ - sn * vq_;
                V[k][q] = sn * vp_ + c * vq_;
            }
        }
    }

    float lam[3] = {K[0][0], K[1][1], K[2][2]};
    int imin = 0;
    if (lam[1] < lam[imin]) imin = 1;
    if (lam[2] < lam[imin]) imin = 2;

    float detH = H[0][0]*(H[1][1]*H[2][2] - H[1][2]*H[2][1])
               - H[0][1]*(H[1][0]*H[2][2] - H[1][2]*H[2][0])
               + H[0][2]*(H[1][0]*H[2][1] - H[1][1]*H[2][0]);

    float R[3][3] = {{0,0,0},{0,0,0},{0,0,0}};
#pragma unroll
    for (int k = 0; k < 3; k++) {
        float v0 = V[0][k], v1 = V[1][k], v2 = V[2][k];
        float hv0 = H[0][0]*v0 + H[0][1]*v1 + H[0][2]*v2;   // sigma_k * u_k
        float hv1 = H[1][0]*v0 + H[1][1]*v1 + H[1][2]*v2;
        float hv2 = H[2][0]*v0 + H[2][1]*v1 + H[2][2]*v2;
        float coef = rsqrtf(fmaxf(lam[k], 1e-30f));
        if (k == imin && detH < 0.0f) coef = -coef;
        R[0][0] += coef * v0 * hv0; R[0][1] += coef * v0 * hv1; R[0][2] += coef * v0 * hv2;
        R[1][0] += coef * v1 * hv0; R[1][1] += coef * v1 * hv1; R[1][2] += coef * v1 * hv2;
        R[2][0] += coef * v2 * hv0; R[2][1] += coef * v2 * hv1; R[2][2] += coef * v2 * hv2;
    }

    float cA0 = sA[0]*invN, cA1 = sA[1]*invN, cA2 = sA[2]*invN;
    float cB0 = sB[0]*invN, cB1 = sB[1]*invN, cB2 = sB[2]*invN;

#pragma unroll
    for (int i = 0; i < 3; i++)
#pragma unroll
        for (int j = 0; j < 3; j++)
            rt[i * 3 + j] = R[i][j];
    rt[9]  = cB0 - (R[0][0]*cA0 + R[0][1]*cA1 + R[0][2]*cA2);
    rt[10] = cB1 - (R[1][0]*cA0 + R[1][1]*cA1 + R[1][2]*cA2);
    rt[11] = cB2 - (R[2][0]*cA0 + R[2][1]*cA1 + R[2][2]*cA2);
}

// ---------------------------------------------------------------------------
// Kernel 1: per-batch reduction of 15 covariance terms + fused Kabsch solve.
// One block per batch, 512 threads, front-batched float4 loads (R8 shape).
// ---------------------------------------------------------------------------
__global__ __launch_bounds__(THREADS) void k1_cov(const float* __restrict__ pred,
                                                  const float* __restrict__ truep) {
    const int b = blockIdx.x;
    const float* pp = pred  + (size_t)b * NPTS * 3;
    const float* qq = truep + (size_t)b * NPTS * 3;

    float sA0=0.f,sA1=0.f,sA2=0.f,sB0=0.f,sB1=0.f,sB2=0.f;
    float m00=0.f,m01=0.f,m02=0.f,m10=0.f,m11=0.f,m12=0.f,m20=0.f,m21=0.f,m22=0.f;

    // Front-batch all loads: 4 fully-unrolled iterations x 6 float4 = 24 LDG.128
    float4 A[ITERS][3], Bv[ITERS][3];
#pragma unroll
    for (int it = 0; it < ITERS; it++) {
        const int c = threadIdx.x + it * THREADS;
        const float4* vp = reinterpret_cast<const float4*>(pp + c * 12);
        const float4* vq = reinterpret_cast<const float4*>(qq + c * 12);
        A[it][0] = vp[0]; A[it][1] = vp[1]; A[it][2] = vp[2];
        Bv[it][0] = vq[0]; Bv[it][1] = vq[1]; Bv[it][2] = vq[2];
    }
#pragma unroll
    for (int it = 0; it < ITERS; it++) {
        float4 a0 = A[it][0], a1 = A[it][1], a2 = A[it][2];
        float4 b0 = Bv[it][0], b1 = Bv[it][1], b2 = Bv[it][2];
        float px[4] = {a0.x, a0.w, a1.z, a2.y};
        float py[4] = {a0.y, a1.x, a1.w, a2.z};
        float pz[4] = {a0.z, a1.y, a2.x, a2.w};
        float qx[4] = {b0.x, b0.w, b1.z, b2.y};
        float qy[4] = {b0.y, b1.x, b1.w, b2.z};
        float qz[4] = {b0.z, b1.y, b2.x, b2.w};
#pragma unroll
        for (int i = 0; i < 4; i++) {
            sA0 += px[i]; sA1 += py[i]; sA2 += pz[i];
            sB0 += qx[i]; sB1 += qy[i]; sB2 += qz[i];
            m00 += px[i]*qx[i]; m01 += px[i]*qy[i]; m02 += px[i]*qz[i];
            m10 += py[i]*qx[i]; m11 += py[i]*qy[i]; m12 += py[i]*qz[i];
            m20 += pz[i]*qx[i]; m21 += pz[i]*qy[i]; m22 += pz[i]*qz[i];
        }
    }

    __shared__ float ws[16][15];
    __shared__ float sh15[15];
    float vals[15] = {sA0,sA1,sA2,sB0,sB1,sB2,m00,m01,m02,m10,m11,m12,m20,m21,m22};
    const int lane = threadIdx.x & 31, w = threadIdx.x >> 5;
#pragma unroll
    for (int q = 0; q < 15; q++) {
        float r = warpSum(vals[q]);
        if (lane == 0) ws[w][q] = r;
    }
    __syncthreads();
    if (threadIdx.x < 15) {
        float tot = 0.f;
#pragma unroll
        for (int i = 0; i < 16; i++) tot += ws[i][threadIdx.x];
        sh15[threadIdx.x] = tot;
    }
    __syncthreads();

    // Fused per-batch Kabsch solve (thread 0; hidden by other blocks' streaming)
    if (threadIdx.x == 0) {
        kabsch_solve(sh15, &d_RT[b * 12]);
    }
}

// ---------------------------------------------------------------------------
// Kernel 2: apply (R, t), clamped distances, per-batch sum, fused final mean.
// R,t read via uniform __ldg (no smem broadcast, no prologue barrier -> the
// 24 data LDGs issue immediately, not fenced behind the RT round-trip).
// aligned_j = sum_i p_i * R[i][j] + t[j]   (pred @ R, as in reference)
// ---------------------------------------------------------------------------
__global__ __launch_bounds__(THREADS) void k3_dist(const float* __restrict__ pred,
                                                   const float* __restrict__ truep,
                                                   float* __restrict__ out) {
    const int b = blockIdx.x;
    const float* pp = pred  + (size_t)b * NPTS * 3;
    const float* qq = truep + (size_t)b * NPTS * 3;
    const float* rt = &d_RT[b * 12];

    const float R00=__ldg(rt+0), R01=__ldg(rt+1), R02=__ldg(rt+2),
                R10=__ldg(rt+3), R11=__ldg(rt+4), R12=__ldg(rt+5),
                R20=__ldg(rt+6), R21=__ldg(rt+7), R22=__ldg(rt+8),
                t0 =__ldg(rt+9), t1 =__ldg(rt+10), t2 =__ldg(rt+11);

    float acc = 0.f;
#pragma unroll
    for (int it = 0; it < ITERS; it++) {
        const int c = threadIdx.x + it * THREADS;
        const float4* vp = reinterpret_cast<const float4*>(pp + c * 12);
        const float4* vq = reinterpret_cast<const float4*>(qq + c * 12);
        float4 a0 = vp[0], a1 = vp[1], a2 = vp[2];
        float4 b0 = vq[0], b1 = vq[1], b2 = vq[2];
        float px[4] = {a0.x, a0.w, a1.z, a2.y};
        float py[4] = {a0.y, a1.x, a1.w, a2.z};
        float pz[4] = {a0.z, a1.y, a2.x, a2.w};
        float qx[4] = {b0.x, b0.w, b1.z, b2.y};
        float qy[4] = {b0.y, b1.x, b1.w, b2.z};
        float qz[4] = {b0.z, b1.y, b2.x, b2.w};
#pragma unroll
        for (int i = 0; i < 4; i++) {
            float dx = px[i]*R00 + py[i]*R10 + pz[i]*R20 + t0 - qx[i];
            float dy = px[i]*R01 + py[i]*R11 + pz[i]*R21 + t1 - qy[i];
            float dz = px[i]*R02 + py[i]*R12 + pz[i]*R22 + t2 - qz[i];
            float d = sqrtf(dx*dx + dy*dy + dz*dz);
            acc += fminf(d, CLAMP_V);
        }
    }

    __shared__ float ws[16];
    __shared__ bool  amLast;
    const int lane = threadIdx.x & 31, w = threadIdx.x >> 5;
    float r = warpSum(acc);
    if (lane == 0) ws[w] = r;
    __syncthreads();
    if (threadIdx.x == 0) {
        float t = 0.f;
#pragma unroll
        for (int i = 0; i < 16; i++) t += ws[i];
        d_partial[b] = t;
        __threadfence();
        int prev = atomicAdd(&d_count, 1);
        amLast = (prev == BATCH - 1);
    }
    __syncthreads();

    // Deterministic final reduce by the last-arriving block (fixed order).
    if (amLast) {
        __threadfence();
        float v = (threadIdx.x < BATCH) ? d_partial[threadIdx.x] : 0.f;
        __shared__ float fs[16];
        float rr = warpSum(v);
        if (lane == 0) fs[w] = rr;
        __syncthreads();
        if (threadIdx.x == 0) {
            float tot = 0.f;
#pragma unroll
            for (int i = 0; i < 8; i++) tot += fs[i];   // first 8 warps hold 256 values
            out[0] = tot / ((float)BATCH * (float)NPTS);
            d_count = 0;                                // reset for next replay
        }
    }
}

extern "C" void kernel_launch(void* const* d_in, const int* in_sizes, int n_in,
                              void* d_out, int out_size) {
    // Inputs in metadata order: pred_frames, true_frames, pred_pos, true_pos.
    // Select the two [B,N,3] arrays (size B*N*3) in order; frames stay untouched.
    const int POS_ELEMS = BATCH * NPTS * 3;
    const float* pred_pos = nullptr;
    const float* true_pos = nullptr;
    for (int i = 0; i < n_in; i++) {
        if (in_sizes[i] == POS_ELEMS) {
            if (!pred_pos)      pred_pos = (const float*)d_in[i];
            else if (!true_pos) true_pos = (const float*)d_in[i];
        }
    }
    if (!pred_pos || !true_pos) {
        pred_pos = (const float*)d_in[2];
        true_pos = (const float*)d_in[3];
    }

    k1_cov <<<BATCH, THREADS>>>(pred_pos, true_pos);
    k3_dist<<<BATCH, THREADS>>>(pred_pos, true_pos, (float*)d_out);
}

// round 16
// speedup vs baseline: 1.7382x; 1.4443x over previous
#include <cuda_runtime.h>
#include <cuda_bf16.h>
#include <math.h>

#define BATCH   256
#define NPTS    8192
#define THREADS 512
#define NCH     ((NPTS * 3) / 12)        // 2048 chunks of 4 points
#define ITERS   (NCH / THREADS)          // 4
#define CLAMP_V 10.0f

// Scratch (no allocations allowed -> __device__ globals)
__device__ float d_RT[BATCH * 12];       // per batch: R row-major [9], t [3]
__device__ float d_partial[BATCH];       // per-batch clamped-distance sums
__device__ int   d_count;                // last-block counter (reset each replay)

__device__ __forceinline__ float warpSum(float v) {
#pragma unroll
    for (int o = 16; o; o >>= 1) v += __shfl_down_sync(0xffffffffu, v, o);
    return v;
}

// ---------------------------------------------------------------------------
// fp32 Kabsch solve from the 15 reduced sums (single thread).
// H = M - sumA sumB^T / N ; Jacobi eig of K = H^T H -> V, lam ; u_k = H v_k/sig
// R = sum_k s_k v_k u_k^T (sign flip on SMALLEST sigma iff det(H) < 0)
// == V diag(1,1,s) U^T as in the reference. t = cB - R cA.
// 5 sweeps + __fdividef (validated R15: rel_err 1.09e-5) -> short serial tail.
// ---------------------------------------------------------------------------
__device__ void kabsch_solve(const float* __restrict__ s, float* __restrict__ rt) {
    const float invN = 1.0f / (float)NPTS;
    float sA[3] = {s[0], s[1], s[2]};
    float sB[3] = {s[3], s[4], s[5]};
    float H[3][3];
#pragma unroll
    for (int i = 0; i < 3; i++)
#pragma unroll
        for (int j = 0; j < 3; j++)
            H[i][j] = s[6 + i * 3 + j] - sA[i] * sB[j] * invN;

    float K[3][3];
#pragma unroll
    for (int i = 0; i < 3; i++)
#pragma unroll
        for (int j = 0; j < 3; j++)
            K[i][j] = H[0][i]*H[0][j] + H[1][i]*H[1][j] + H[2][i]*H[2][j];

    float V[3][3] = {{1,0,0},{0,1,0},{0,0,1}};
    const int PP[3] = {0, 0, 1};
    const int QQ[3] = {1, 2, 2};
    for (int sweep = 0; sweep < 5; sweep++) {
#pragma unroll
        for (int pair = 0; pair < 3; pair++) {
            const int p = PP[pair], q = QQ[pair];
            float apq = K[p][q];
            if (fabsf(apq) <= 1e-10f * (fabsf(K[p][p]) + fabsf(K[q][q]))) continue;
            float theta = __fdividef(K[q][q] - K[p][p], 2.0f * apq);
            float den = (theta >= 0.0f) ? (theta + sqrtf(1.0f + theta * theta))
                                        : (theta - sqrtf(1.0f + theta * theta));
            float t = __fdividef(1.0f, den);
            float c = rsqrtf(1.0f + t * t);
            float sn = t * c;
#pragma unroll
            for (int k = 0; k < 3; k++) {
                float kp = K[k][p], kq = K[k][q];
                K[k][p] = c * kp - sn * kq;
                K[k][q] = sn * kp + c * kq;
            }
#pragma unroll
            for (int k = 0; k < 3; k++) {
                float pk = K[p][k], qk = K[q][k];
                K[p][k] = c * pk - sn * qk;
                K[q][k] = sn * pk + c * qk;
            }
#pragma unroll
            for (int k = 0; k < 3; k++) {
                float vp_ = V[k][p], vq_ = V[k][q];
                V[k][p] = c * vp_ - sn * vq_;
                V[k][q] = sn * vp_ + c * vq_;
            }
        }
    }

    float lam[3] = {K[0][0], K[1][1], K[2][2]};
    int imin = 0;
    if (lam[1] < lam[imin]) imin = 1;
    if (lam[2] < lam[imin]) imin = 2;

    float detH = H[0][0]*(H[1][1]*H[2][2] - H[1][2]*H[2][1])
               - H[0][1]*(H[1][0]*H[2][2] - H[1][2]*H[2][0])
               + H[0][2]*(H[1][0]*H[2][1] - H[1][1]*H[2][0]);

    float R[3][3] = {{0,0,0},{0,0,0},{0,0,0}};
#pragma unroll
    for (int k = 0; k < 3; k++) {
        float v0 = V[0][k], v1 = V[1][k], v2 = V[2][k];
        float hv0 = H[0][0]*v0 + H[0][1]*v1 + H[0][2]*v2;   // sigma_k * u_k
        float hv1 = H[1][0]*v0 + H[1][1]*v1 + H[1][2]*v2;
        float hv2 = H[2][0]*v0 + H[2][1]*v1 + H[2][2]*v2;
        float coef = rsqrtf(fmaxf(lam[k], 1e-30f));
        if (k == imin && detH < 0.0f) coef = -coef;
        R[0][0] += coef * v0 * hv0; R[0][1] += coef * v0 * hv1; R[0][2] += coef * v0 * hv2;
        R[1][0] += coef * v1 * hv0; R[1][1] += coef * v1 * hv1; R[1][2] += coef * v1 * hv2;
        R[2][0] += coef * v2 * hv0; R[2][1] += coef * v2 * hv1; R[2][2] += coef * v2 * hv2;
    }

    float cA0 = sA[0]*invN, cA1 = sA[1]*invN, cA2 = sA[2]*invN;
    float cB0 = sB[0]*invN, cB1 = sB[1]*invN, cB2 = sB[2]*invN;

#pragma unroll
    for (int i = 0; i < 3; i++)
#pragma unroll
        for (int j = 0; j < 3; j++)
            rt[i * 3 + j] = R[i][j];
    rt[9]  = cB0 - (R[0][0]*cA0 + R[0][1]*cA1 + R[0][2]*cA2);
    rt[10] = cB1 - (R[1][0]*cA0 + R[1][1]*cA1 + R[1][2]*cA2);
    rt[11] = cB2 - (R[2][0]*cA0 + R[2][1]*cA1 + R[2][2]*cA2);
}

// ---------------------------------------------------------------------------
// Kernel 1: per-batch reduction of 15 covariance terms + fused Kabsch solve.
// One block per batch, 512 threads, front-batched float4 loads (R8 shape).
// ---------------------------------------------------------------------------
__global__ __launch_bounds__(THREADS) void k1_cov(const float* __restrict__ pred,
                                                  const float* __restrict__ truep) {
    const int b = blockIdx.x;
    const float* pp = pred  + (size_t)b * NPTS * 3;
    const float* qq = truep + (size_t)b * NPTS * 3;

    float sA0=0.f,sA1=0.f,sA2=0.f,sB0=0.f,sB1=0.f,sB2=0.f;
    float m00=0.f,m01=0.f,m02=0.f,m10=0.f,m11=0.f,m12=0.f,m20=0.f,m21=0.f,m22=0.f;

    // Front-batch all loads: 4 fully-unrolled iterations x 6 float4 = 24 LDG.128
    float4 A[ITERS][3], Bv[ITERS][3];
#pragma unroll
    for (int it = 0; it < ITERS; it++) {
        const int c = threadIdx.x + it * THREADS;
        const float4* vp = reinterpret_cast<const float4*>(pp + c * 12);
        const float4* vq = reinterpret_cast<const float4*>(qq + c * 12);
        A[it][0] = vp[0]; A[it][1] = vp[1]; A[it][2] = vp[2];
        Bv[it][0] = vq[0]; Bv[it][1] = vq[1]; Bv[it][2] = vq[2];
    }
#pragma unroll
    for (int it = 0; it < ITERS; it++) {
        float4 a0 = A[it][0], a1 = A[it][1], a2 = A[it][2];
        float4 b0 = Bv[it][0], b1 = Bv[it][1], b2 = Bv[it][2];
        float px[4] = {a0.x, a0.w, a1.z, a2.y};
        float py[4] = {a0.y, a1.x, a1.w, a2.z};
        float pz[4] = {a0.z, a1.y, a2.x, a2.w};
        float qx[4] = {b0.x, b0.w, b1.z, b2.y};
        float qy[4] = {b0.y, b1.x, b1.w, b2.z};
        float qz[4] = {b0.z, b1.y, b2.x, b2.w};
#pragma unroll
        for (int i = 0; i < 4; i++) {
            sA0 += px[i]; sA1 += py[i]; sA2 += pz[i];
            sB0 += qx[i]; sB1 += qy[i]; sB2 += qz[i];
            m00 += px[i]*qx[i]; m01 += px[i]*qy[i]; m02 += px[i]*qz[i];
            m10 += py[i]*qx[i]; m11 += py[i]*qy[i]; m12 += py[i]*qz[i];
            m20 += pz[i]*qx[i]; m21 += pz[i]*qy[i]; m22 += pz[i]*qz[i];
        }
    }

    __shared__ float ws[16][15];
    __shared__ float sh15[15];
    float vals[15] = {sA0,sA1,sA2,sB0,sB1,sB2,m00,m01,m02,m10,m11,m12,m20,m21,m22};
    const int lane = threadIdx.x & 31, w = threadIdx.x >> 5;
#pragma unroll
    for (int q = 0; q < 15; q++) {
        float r = warpSum(vals[q]);
        if (lane == 0) ws[w][q] = r;
    }
    __syncthreads();
    if (threadIdx.x < 15) {
        float tot = 0.f;
#pragma unroll
        for (int i = 0; i < 16; i++) tot += ws[i][threadIdx.x];
        sh15[threadIdx.x] = tot;
    }
    __syncthreads();

    // Fused per-batch Kabsch solve (thread 0; hidden by other blocks' streaming)
    if (threadIdx.x == 0) {
        kabsch_solve(sh15, &d_RT[b * 12]);
    }
}

// ---------------------------------------------------------------------------
// Kernel 2: apply (R, t), clamped distances, per-batch sum, fused final mean.
// Plain PDL: grid-dependency sync at entry (no state held across it -> regs
// stay ~40); blocks become resident early and start the moment k1 completes.
// R,t via smem broadcast (measured best in R8: k3 13.2us vs 15.8 with __ldg).
// aligned_j = sum_i p_i * R[i][j] + t[j]   (pred @ R, as in reference)
// ---------------------------------------------------------------------------
__global__ __launch_bounds__(THREADS) void k3_dist(const float* __restrict__ pred,
                                                   const float* __restrict__ truep,
                                                   float* __restrict__ out) {
    cudaGridDependencySynchronize();        // wait for k1 grid (d_RT ready)

    const int b = blockIdx.x;
    __shared__ float sRT[12];
    if (threadIdx.x < 12) sRT[threadIdx.x] = d_RT[b * 12 + threadIdx.x];
    __syncthreads();
    const float R00=sRT[0], R01=sRT[1], R02=sRT[2],
                R10=sRT[3], R11=sRT[4], R12=sRT[5],
                R20=sRT[6], R21=sRT[7], R22=sRT[8],
                t0 =sRT[9], t1 =sRT[10], t2 =sRT[11];

    const float* pp = pred  + (size_t)b * NPTS * 3;
    const float* qq = truep + (size_t)b * NPTS * 3;

    float acc = 0.f;
#pragma unroll
    for (int it = 0; it < ITERS; it++) {
        const int c = threadIdx.x + it * THREADS;
        const float4* vp = reinterpret_cast<const float4*>(pp + c * 12);
        const float4* vq = reinterpret_cast<const float4*>(qq + c * 12);
        float4 a0 = vp[0], a1 = vp[1], a2 = vp[2];
        float4 b0 = vq[0], b1 = vq[1], b2 = vq[2];
        float px[4] = {a0.x, a0.w, a1.z, a2.y};
        float py[4] = {a0.y, a1.x, a1.w, a2.z};
        float pz[4] = {a0.z, a1.y, a2.x, a2.w};
        float qx[4] = {b0.x, b0.w, b1.z, b2.y};
        float qy[4] = {b0.y, b1.x, b1.w, b2.z};
        float qz[4] = {b0.z, b1.y, b2.x, b2.w};
#pragma unroll
        for (int i = 0; i < 4; i++) {
            float dx = px[i]*R00 + py[i]*R10 + pz[i]*R20 + t0 - qx[i];
            float dy = px[i]*R01 + py[i]*R11 + pz[i]*R21 + t1 - qy[i];
            float dz = px[i]*R02 + py[i]*R12 + pz[i]*R22 + t2 - qz[i];
            float d = sqrtf(dx*dx + dy*dy + dz*dz);
            acc += fminf(d, CLAMP_V);
        }
    }

    __shared__ float ws[16];
    __shared__ bool  amLast;
    const int lane = threadIdx.x & 31, w = threadIdx.x >> 5;
    float r = warpSum(acc);
    if (lane == 0) ws[w] = r;
    __syncthreads();
    if (threadIdx.x == 0) {
        float t = 0.f;
#pragma unroll
        for (int i = 0; i < 16; i++) t += ws[i];
        d_partial[b] = t;
        __threadfence();
        int prev = atomicAdd(&d_count, 1);
        amLast = (prev == BATCH - 1);
    }
    __syncthreads();

    // Deterministic final reduce by the last-arriving block (fixed order).
    if (amLast) {
        __threadfence();
        float v = (threadIdx.x < BATCH) ? d_partial[threadIdx.x] : 0.f;
        __shared__ float fs[16];
        float rr = warpSum(v);
        if (lane == 0) fs[w] = rr;
        __syncthreads();
        if (threadIdx.x == 0) {
            float tot = 0.f;
#pragma unroll
            for (int i = 0; i < 8; i++) tot += fs[i];   // first 8 warps hold 256 values
            out[0] = tot / ((float)BATCH * (float)NPTS);
            d_count = 0;                                // reset for next replay
        }
    }
}

extern "C" void kernel_launch(void* const* d_in, const int* in_sizes, int n_in,
                              void* d_out, int out_size) {
    // Inputs in metadata order: pred_frames, true_frames, pred_pos, true_pos.
    // Select the two [B,N,3] arrays (size B*N*3) in order; frames stay untouched.
    const int POS_ELEMS = BATCH * NPTS * 3;
    const float* pred_pos = nullptr;
    const float* true_pos = nullptr;
    for (int i = 0; i < n_in; i++) {
        if (in_sizes[i] == POS_ELEMS) {
            if (!pred_pos)      pred_pos = (const float*)d_in[i];
            else if (!true_pos) true_pos = (const float*)d_in[i];
        }
    }
    if (!pred_pos || !true_pos) {
        pred_pos = (const float*)d_in[2];
        true_pos = (const float*)d_in[3];
    }

    k1_cov<<<BATCH, THREADS>>>(pred_pos, true_pos);

    // k3 with programmatic dependent launch (sync at kernel entry, no
    // prefetch across it): blocks become resident during k1's tail and fire
    // immediately on k1 completion.
    cudaLaunchConfig_t cfg = {};
    cfg.gridDim  = dim3(BATCH, 1, 1);
    cfg.blockDim = dim3(THREADS, 1, 1);
    cfg.dynamicSmemBytes = 0;
    cfg.stream = 0;
    cudaLaunchAttribute attr[1];
    attr[0].id = cudaLaunchAttributeProgrammaticStreamSerialization;
    attr[0].val.programmaticStreamSerializationAllowed = 1;
    cfg.attrs = attr;
    cfg.numAttrs = 1;
    cudaLaunchKernelEx(&cfg, k3_dist, pred_pos, true_pos, (float*)d_out);
}

// round 17
// speedup vs baseline: 1.7411x; 1.0017x over previous
#include <cuda_runtime.h>
#include <cuda_bf16.h>
#include <math.h>

#define BATCH   256
#define NPTS    8192
#define THREADS 512
#define GRID    (2 * BATCH)              // 256 producers + 256 consumers
#define NCH     ((NPTS * 3) / 12)        // 2048 chunks of 4 points per batch
#define ITERS   (NCH / THREADS)          // 4
#define CLAMP_V 10.0f

// Scratch (no allocations allowed -> __device__ globals, zero-initialized)
__device__ float d_RT[BATCH * 12];       // per batch: R row-major [9], t [3]
__device__ int   d_flag[BATCH];          // per-batch ready flags (reset by consumer)
__device__ float d_partial[BATCH];       // per-batch clamped-distance sums
__device__ int   d_count;                // consumer arrival counter (reset each replay)

__device__ __forceinline__ float warpSum(float v) {
#pragma unroll
    for (int o = 16; o; o >>= 1) v += __shfl_down_sync(0xffffffffu, v, o);
    return v;
}

// ---------------------------------------------------------------------------
// fp32 Kabsch solve from the 15 reduced sums (single thread).
// H = M - sumA sumB^T / N ; Jacobi eig of K = H^T H -> V, lam ; u_k = H v_k/sig
// R = sum_k s_k v_k u_k^T (sign flip on SMALLEST sigma iff det(H) < 0)
// == V diag(1,1,s) U^T as in the reference. t = cB - R cA.
// 5 sweeps + __fdividef (validated R15/R16: rel_err 1.09e-5).
// ---------------------------------------------------------------------------
__device__ void kabsch_solve(const float* __restrict__ s, float* __restrict__ rt) {
    const float invN = 1.0f / (float)NPTS;
    float sA[3] = {s[0], s[1], s[2]};
    float sB[3] = {s[3], s[4], s[5]};
    float H[3][3];
#pragma unroll
    for (int i = 0; i < 3; i++)
#pragma unroll
        for (int j = 0; j < 3; j++)
            H[i][j] = s[6 + i * 3 + j] - sA[i] * sB[j] * invN;

    float K[3][3];
#pragma unroll
    for (int i = 0; i < 3; i++)
#pragma unroll
        for (int j = 0; j < 3; j++)
            K[i][j] = H[0][i]*H[0][j] + H[1][i]*H[1][j] + H[2][i]*H[2][j];

    float V[3][3] = {{1,0,0},{0,1,0},{0,0,1}};
    const int PP[3] = {0, 0, 1};
    const int QQ[3] = {1, 2, 2};
    for (int sweep = 0; sweep < 5; sweep++) {
#pragma unroll
        for (int pair = 0; pair < 3; pair++) {
            const int p = PP[pair], q = QQ[pair];
            float apq = K[p][q];
            if (fabsf(apq) <= 1e-10f * (fabsf(K[p][p]) + fabsf(K[q][q]))) continue;
            float theta = __fdividef(K[q][q] - K[p][p], 2.0f * apq);
            float den = (theta >= 0.0f) ? (theta + sqrtf(1.0f + theta * theta))
                                        : (theta - sqrtf(1.0f + theta * theta));
            float t = __fdividef(1.0f, den);
            float c = rsqrtf(1.0f + t * t);
            float sn = t * c;
#pragma unroll
            for (int k = 0; k < 3; k++) {
                float kp = K[k][p], kq = K[k][q];
                K[k][p] = c * kp - sn * kq;
                K[k][q] = sn * kp + c * kq;
            }
#pragma unroll
            for (int k = 0; k < 3; k++) {
                float pk = K[p][k], qk = K[q][k];
                K[p][k] = c * pk - sn * qk;
                K[q][k] = sn * pk + c * qk;
            }
#pragma unroll
            for (int k = 0; k < 3; k++) {
                float vp_ = V[k][p], vq_ = V[k][q];
                V[k][p] = c * vp_ - sn * vq_;
                V[k][q] = sn * vp_ + c * vq_;
            }
        }
    }

    float lam[3] = {K[0][0], K[1][1], K[2][2]};
    int imin = 0;
    if (lam[1] < lam[imin]) imin = 1;
    if (lam[2] < lam[imin]) imin = 2;

    float detH = H[0][0]*(H[1][1]*H[2][2] - H[1][2]*H[2][1])
               - H[0][1]*(H[1][0]*H[2][2] - H[1][2]*H[2][0])
               + H[0][2]*(H[1][0]*H[2][1] - H[1][1]*H[2][0]);

    float R[3][3] = {{0,0,0},{0,0,0},{0,0,0}};
#pragma unroll
    for (int k = 0; k < 3; k++) {
        float v0 = V[0][k], v1 = V[1][k], v2 = V[2][k];
        float hv0 = H[0][0]*v0 + H[0][1]*v1 + H[0][2]*v2;   // sigma_k * u_k
        float hv1 = H[1][0]*v0 + H[1][1]*v1 + H[1][2]*v2;
        float hv2 = H[2][0]*v0 + H[2][1]*v1 + H[2][2]*v2;
        float coef = rsqrtf(fmaxf(lam[k], 1e-30f));
        if (k == imin && detH < 0.0f) coef = -coef;
        R[0][0] += coef * v0 * hv0; R[0][1] += coef * v0 * hv1; R[0][2] += coef * v0 * hv2;
        R[1][0] += coef * v1 * hv0; R[1][1] += coef * v1 * hv1; R[1][2] += coef * v1 * hv2;
        R[2][0] += coef * v2 * hv0; R[2][1] += coef * v2 * hv1; R[2][2] += coef * v2 * hv2;
    }

    float cA0 = sA[0]*invN, cA1 = sA[1]*invN, cA2 = sA[2]*invN;
    float cB0 = sB[0]*invN, cB1 = sB[1]*invN, cB2 = sB[2]*invN;

#pragma unroll
    for (int i = 0; i < 3; i++)
#pragma unroll
        for (int j = 0; j < 3; j++)
            rt[i * 3 + j] = R[i][j];
    rt[9]  = cB0 - (R[0][0]*cA0 + R[0][1]*cA1 + R[0][2]*cA2);
    rt[10] = cB1 - (R[1][0]*cA0 + R[1][1]*cA1 + R[1][2]*cA2);
    rt[11] = cB2 - (R[2][0]*cA0 + R[2][1]*cA1 + R[2][2]*cA2);
}

// ---------------------------------------------------------------------------
// Single-launch producer-consumer kernel.
// Blocks [0, 256):   producer for batch b = bid   -- R8 k1 body, then flag.
// Blocks [256, 512): consumer for batch b = bid-256 -- spin on flag, R8 k3 body.
// All 256 producers fit in wave 1 (capacity 296 CTAs) -> no deadlock; consumer
// b starts right after producer b -> batch data L2-hot, phases pipeline.
// ---------------------------------------------------------------------------
__global__ __launch_bounds__(THREADS, 2)
void fape_pc(const float* __restrict__ pred, const float* __restrict__ truep,
             float* __restrict__ out) {
    const int bid = blockIdx.x;
    const int lane = threadIdx.x & 31, w = threadIdx.x >> 5;

    if (bid < BATCH) {
        // ================= PRODUCER: covariance + Kabsch solve =================
        const int b = bid;
        const float* pp = pred  + (size_t)b * NPTS * 3;
        const float* qq = truep + (size_t)b * NPTS * 3;

        float sA0=0.f,sA1=0.f,sA2=0.f,sB0=0.f,sB1=0.f,sB2=0.f;
        float m00=0.f,m01=0.f,m02=0.f,m10=0.f,m11=0.f,m12=0.f,m20=0.f,m21=0.f,m22=0.f;

        // Front-batch all loads: 4 iterations x 6 float4 = 24 LDG.128
        float4 A[ITERS][3], Bv[ITERS][3];
#pragma unroll
        for (int it = 0; it < ITERS; it++) {
            const int c = threadIdx.x + it * THREADS;
            const float4* vp = reinterpret_cast<const float4*>(pp + c * 12);
            const float4* vq = reinterpret_cast<const float4*>(qq + c * 12);
            A[it][0] = vp[0]; A[it][1] = vp[1]; A[it][2] = vp[2];
            Bv[it][0] = vq[0]; Bv[it][1] = vq[1]; Bv[it][2] = vq[2];
        }
#pragma unroll
        for (int it = 0; it < ITERS; it++) {
            float4 a0 = A[it][0], a1 = A[it][1], a2 = A[it][2];
            float4 b0 = Bv[it][0], b1 = Bv[it][1], b2 = Bv[it][2];
            float px[4] = {a0.x, a0.w, a1.z, a2.y};
            float py[4] = {a0.y, a1.x, a1.w, a2.z};
            float pz[4] = {a0.z, a1.y, a2.x, a2.w};
            float qx[4] = {b0.x, b0.w, b1.z, b2.y};
            float qy[4] = {b0.y, b1.x, b1.w, b2.z};
            float qz[4] = {b0.z, b1.y, b2.x, b2.w};
#pragma unroll
            for (int i = 0; i < 4; i++) {
                sA0 += px[i]; sA1 += py[i]; sA2 += pz[i];
                sB0 += qx[i]; sB1 += qy[i]; sB2 += qz[i];
                m00 += px[i]*qx[i]; m01 += px[i]*qy[i]; m02 += px[i]*qz[i];
                m10 += py[i]*qx[i]; m11 += py[i]*qy[i]; m12 += py[i]*qz[i];
                m20 += pz[i]*qx[i]; m21 += pz[i]*qy[i]; m22 += pz[i]*qz[i];
            }
        }

        __shared__ float ws[16][15];
        __shared__ float sh15[15];
        float vals[15] = {sA0,sA1,sA2,sB0,sB1,sB2,m00,m01,m02,m10,m11,m12,m20,m21,m22};
#pragma unroll
        for (int q = 0; q < 15; q++) {
            float r = warpSum(vals[q]);
            if (lane == 0) ws[w][q] = r;
        }
        __syncthreads();
        if (threadIdx.x < 15) {
            float tot = 0.f;
#pragma unroll
            for (int i = 0; i < 16; i++) tot += ws[i][threadIdx.x];
            sh15[threadIdx.x] = tot;
        }
        __syncthreads();

        if (threadIdx.x == 0) {
            kabsch_solve(sh15, &d_RT[b * 12]);
            __threadfence();                       // publish d_RT before flag
            atomicExch(&d_flag[b], 1);             // release
        }
    } else {
        // ================= CONSUMER: distances for batch b =================
        const int b = bid - BATCH;

        if (threadIdx.x == 0) {
            // Spin until producer b published R,t. nanosleep keeps issue
            // pressure off co-resident producer warps.
            while (atomicAdd(&d_flag[b], 0) == 0) __nanosleep(64);
            d_flag[b] = 0;                         // reset for next graph replay
        }
        __syncthreads();
        __threadfence();                           // acquire d_RT

        __shared__ float sRT[12];
        if (threadIdx.x < 12) sRT[threadIdx.x] = d_RT[b * 12 + threadIdx.x];
        __syncthreads();
        const float R00=sRT[0], R01=sRT[1], R02=sRT[2],
                    R10=sRT[3], R11=sRT[4], R12=sRT[5],
                    R20=sRT[6], R21=sRT[7], R22=sRT[8],
                    t0 =sRT[9], t1 =sRT[10], t2 =sRT[11];

        const float* pp = pred  + (size_t)b * NPTS * 3;
        const float* qq = truep + (size_t)b * NPTS * 3;

        float acc = 0.f;
#pragma unroll
        for (int it = 0; it < ITERS; it++) {
            const int c = threadIdx.x + it * THREADS;
            const float4* vp = reinterpret_cast<const float4*>(pp + c * 12);
            const float4* vq = reinterpret_cast<const float4*>(qq + c * 12);
            float4 a0 = vp[0], a1 = vp[1], a2 = vp[2];
            float4 b0 = vq[0], b1 = vq[1], b2 = vq[2];
            float px[4] = {a0.x, a0.w, a1.z, a2.y};
            float py[4] = {a0.y, a1.x, a1.w, a2.z};
            float pz[4] = {a0.z, a1.y, a2.x, a2.w};
            float qx[4] = {b0.x, b0.w, b1.z, b2.y};
            float qy[4] = {b0.y, b1.x, b1.w, b2.z};
            float qz[4] = {b0.z, b1.y, b2.x, b2.w};
#pragma unroll
            for (int i = 0; i < 4; i++) {
                float dx = px[i]*R00 + py[i]*R10 + pz[i]*R20 + t0 - qx[i];
                float dy = px[i]*R01 + py[i]*R11 + pz[i]*R21 + t1 - qy[i];
                float dz = px[i]*R02 + py[i]*R12 + pz[i]*R22 + t2 - qz[i];
                float d = sqrtf(dx*dx + dy*dy + dz*dz);
                acc += fminf(d, CLAMP_V);
            }
        }

        __shared__ float ws2[16];
        __shared__ bool  amLast;
        float r = warpSum(acc);
        if (lane == 0) ws2[w] = r;
        __syncthreads();
        if (threadIdx.x == 0) {
            float t = 0.f;
#pragma unroll
            for (int i = 0; i < 16; i++) t += ws2[i];
            d_partial[b] = t;
            __threadfence();
            int prev = atomicAdd(&d_count, 1);
            amLast = (prev == BATCH - 1);
        }
        __syncthreads();

        // Deterministic final reduce by last-arriving consumer (fixed order).
        if (amLast) {
            __threadfence();
            float v = (threadIdx.x < BATCH) ? d_partial[threadIdx.x] : 0.f;
            __shared__ float fs[16];
            float rr = warpSum(v);
            if (lane == 0) fs[w] = rr;
            __syncthreads();
            if (threadIdx.x == 0) {
                float tot = 0.f;
#pragma unroll
                for (int i = 0; i < 8; i++) tot += fs[i];  // 8 warps hold 256 values
                out[0] = tot / ((float)BATCH * (float)NPTS);
                d_count = 0;                               // reset for next replay
            }
        }
    }
}

extern "C" void kernel_launch(void* const* d_in, const int* in_sizes, int n_in,
                              void* d_out, int out_size) {
    // Inputs in metadata order: pred_frames, true_frames, pred_pos, true_pos.
    // Select the two [B,N,3] arrays (size B*N*3) in order; frames stay untouched.
    const int POS_ELEMS = BATCH * NPTS * 3;
    const float* pred_pos = nullptr;
    const float* true_pos = nullptr;
    for (int i = 0; i < n_in; i++) {
        if (in_sizes[i] == POS_ELEMS) {
            if (!pred_pos)      pred_pos = (const float*)d_in[i];
            else if (!true_pos) true_pos = (const float*)d_in[i];
        }
    }
    if (!pred_pos || !true_pos) {
        pred_pos = (const float*)d_in[2];
        true_pos = (const float*)d_in[3];
    }

    fape_pc<<<GRID, THREADS>>>(pred_pos, true_pos, (float*)d_out);
}